// round 16
// baseline (speedup 1.0000x reference)
#include <cuda_runtime.h>
#include <math.h>

#define DDIM   256
#define BATCH  128
#define SEQ    1024
#define NROWS  (BATCH*SEQ)          // 131072
#define HALF   (NROWS/2)            // 65536
#define NBLK_B 592                  // 148 SMs x 4 blocks: one full resident wave
#define NBLK_C 1184                 // 148 SMs x 4 blocks x 2 exact waves

// ---- scratch (static device globals; no allocation) ----
__device__ __align__(16) float g_part[8*BATCH*DDIM];
__device__ __align__(16) float g_cb[BATCH*DDIM];
__device__ __align__(16) float g_mean[DDIM];
__device__ float g_ic;
__device__ __align__(16) float g_bpS[NBLK_B*DDIM];
__device__ __align__(16) float g_bpQ[NBLK_B*DDIM];
__device__ __align__(16) float g_scale[DDIM];
__device__ float g_ib;
__device__ float g_lab;
__device__ __align__(16) float4 g_rowsc[NROWS];   // per-row (f, gc, c, 0)
__device__ unsigned int g_a2cnt;                   // zero-init; reset after use

__device__ __forceinline__ float warpsum(float v) {
    #pragma unroll
    for (int off = 16; off > 0; off >>= 1)
        v += __shfl_xor_sync(0xffffffffu, v, off);
    return v;
}
__device__ __forceinline__ void warpsum2(float& a, float& b) {
    #pragma unroll
    for (int off = 16; off > 0; off >>= 1) {
        a += __shfl_xor_sync(0xffffffffu, a, off);
        b += __shfl_xor_sync(0xffffffffu, b, off);
    }
}
__device__ __forceinline__ void warpsum4(float& a, float& b, float& c, float& d) {
    #pragma unroll
    for (int off = 16; off > 0; off >>= 1) {
        a += __shfl_xor_sync(0xffffffffu, a, off);
        b += __shfl_xor_sync(0xffffffffu, b, off);
        c += __shfl_xor_sync(0xffffffffu, c, off);
        d += __shfl_xor_sync(0xffffffffu, d, off);
    }
}
__device__ __forceinline__ float blocksum256(float v, float* sh) {
    const int lane = threadIdx.x & 31;
    const int warp = threadIdx.x >> 5;
    float w = warpsum(v);
    if (lane == 0) sh[warp] = w;
    __syncthreads();
    float r = sh[0];
    #pragma unroll
    for (int i = 1; i < 8; i++) r += sh[i];
    return r;
}
__device__ __forceinline__ float acosh_over_s(float alpha) {
    float a2m1 = fmaf(alpha, alpha, -1.0f);
    float r = rsqrtf(a2m1);
    float s = a2m1 * r;
    return __logf(alpha + s) * r;
}

// ---------------------------------------------------------------------------
// Pass A: per-(chunk j, batch b) feature sums over 128 rows of S.
// float4 layout: 256 thr = 64 float4-cols x 4 row-groups of 32 rows.
// ---------------------------------------------------------------------------
__global__ void __launch_bounds__(256) passA_kernel(const float* __restrict__ x) {
    __shared__ float red[4][DDIM];
    const int j    = blockIdx.x;
    const int b    = blockIdx.y;
    const int col4 = threadIdx.x & 63;
    const int rg   = threadIdx.x >> 6;      // 0..3
    const float4* p = reinterpret_cast<const float4*>(
        x + ((size_t)b*SEQ + (size_t)j*128) * DDIM) + (size_t)(rg*32) * 64 + col4;
    float4 acc = make_float4(0.f, 0.f, 0.f, 0.f);
    #pragma unroll 8
    for (int s = 0; s < 32; s++) {
        float4 v = p[(size_t)s * 64];
        acc.x += v.x; acc.y += v.y; acc.z += v.z; acc.w += v.w;
    }
    *reinterpret_cast<float4*>(&red[rg][col4*4]) = acc;
    __syncthreads();
    const int d = threadIdx.x;
    g_part[((size_t)(j*BATCH + b))*DDIM + d] =
        (red[0][d] + red[1][d]) + (red[2][d] + red[3][d]);
}

// ---------------------------------------------------------------------------
// A2 (fused): per-batch centroid (128 blocks); the LAST finishing block also
// performs the batch-level centroid -> g_mean, g_ic (saves one launch).
// ---------------------------------------------------------------------------
__global__ void __launch_bounds__(256) a2_kernel() {
    __shared__ float sh[8];
    __shared__ bool isLast;
    const int b = blockIdx.x;
    const int d = threadIdx.x;
    float a = 0.f;
    #pragma unroll
    for (int j = 0; j < 8; j++)
        a += g_part[(size_t)(j*BATCH + b)*DDIM + d];
    a *= (1.0f / (float)SEQ);
    float p = (d == 0) ? -a*a : a*a;
    float l = blocksum256(p, sh);
    float dn = rsqrtf(fmaxf(fabsf(l), 1e-8f));
    g_cb[(size_t)b*DDIM + d] = a * dn;

    __threadfence();
    if (d == 0) {
        unsigned int c = atomicAdd(&g_a2cnt, 1u);
        isLast = (c == BATCH - 1);
    }
    __syncthreads();
    if (isLast) {
        float s = 0.f;
        #pragma unroll 8
        for (int bb = 0; bb < BATCH; bb++) s += g_cb[(size_t)bb*DDIM + d];
        s *= (1.0f / (float)BATCH);
        float pp = (d == 0) ? -s*s : s*s;
        __syncthreads();
        float ll = blocksum256(pp, sh);
        float dn2 = rsqrtf(fmaxf(fabsf(ll), 1e-8f));
        float mv = s * dn2;
        g_mean[d] = mv;
        if (d == 0) { g_ic = 1.0f / (1.0f + mv); g_a2cnt = 0u; }
    }
}

// ---------------------------------------------------------------------------
// Pass B: per-feature Sum(t), Sum(t^2); 2 rows/warp (idx, idx+HALF),
// descending. Stores per-row scalars (f, gc, c) for pass C reuse.
// ---------------------------------------------------------------------------
__global__ void __launch_bounds__(256) passB_kernel(const float* __restrict__ x) {
    __shared__ float sS[8][DDIM];
    __shared__ float sQ[8][DDIM];
    const int lane = threadIdx.x & 31;
    const int wib  = threadIdx.x >> 5;
    const int gw   = blockIdx.x * 8 + wib;
    const int nw   = NBLK_B * 8;

    float m[8];
    {
        float4 v;
        v = reinterpret_cast<const float4*>(g_mean)[lane];    m[0]=v.x; m[1]=v.y; m[2]=v.z; m[3]=v.w;
        v = reinterpret_cast<const float4*>(g_mean)[lane+32]; m[4]=v.x; m[5]=v.y; m[6]=v.z; m[7]=v.w;
    }
    const float m0 = g_mean[0];
    const float ic = g_ic;

    float sm[8] = {0,0,0,0,0,0,0,0};
    float sq[8] = {0,0,0,0,0,0,0,0};

    for (int idx = gw; idx < HALF; idx += nw) {
        const int row = HALF - 1 - idx;            // descending
        const float4* rp1 = reinterpret_cast<const float4*>(x) + (size_t)row * (DDIM/4);
        const float4* rp2 = rp1 + (size_t)HALF * (DDIM/4);
        float a[8], b[8];
        {
            float4 v1 = rp1[lane], v2 = rp1[lane+32];
            float4 w1 = rp2[lane], w2 = rp2[lane+32];
            a[0]=v1.x; a[1]=v1.y; a[2]=v1.z; a[3]=v1.w;
            a[4]=v2.x; a[5]=v2.y; a[6]=v2.z; a[7]=v2.w;
            b[0]=w1.x; b[1]=w1.y; b[2]=w1.z; b[3]=w1.w;
            b[4]=w2.x; b[5]=w2.y; b[6]=w2.z; b[7]=w2.w;
        }
        float p1 = m[0]*a[0], p2 = m[0]*b[0];
        if (lane == 0) { p1 = -p1; p2 = -p2; }
        #pragma unroll
        for (int k = 1; k < 8; k++) { p1 += m[k]*a[k]; p2 += m[k]*b[k]; }
        float x01 = __shfl_sync(0xffffffffu, a[0], 0);
        float x02 = __shfl_sync(0xffffffffu, b[0], 0);
        warpsum2(p1, p2);
        float al1 = fmaxf(-p1, 1.0f + 1e-7f);
        float al2 = fmaxf(-p2, 1.0f + 1e-7f);
        float f1 = acosh_over_s(al1);
        float f2 = acosh_over_s(al2);
        float c1 = f1 * (x01 - al1*m0) * ic;
        float c2 = f2 * (x02 - al2*m0) * ic;
        float gc1 = fmaf(f1, al1, c1);
        float gc2 = fmaf(f2, al2, c2);
        if (lane == 0) {
            g_rowsc[row]        = make_float4(f1, gc1, c1, 0.f);
            g_rowsc[row + HALF] = make_float4(f2, gc2, c2, 0.f);
        }
        #pragma unroll
        for (int k = 0; k < 8; k++) {
            float t1 = fmaf(f1, a[k], -gc1*m[k]);
            float t2 = fmaf(f2, b[k], -gc2*m[k]);
            if (k == 0 && lane == 0) { t1 -= c1; t2 -= c2; }
            sm[k] += t1 + t2;
            sq[k] += fmaf(t1, t1, t2*t2);
        }
    }

    const int d0i = lane * 4;
    #pragma unroll
    for (int k = 0; k < 4; k++) {
        sS[wib][d0i+k]     = sm[k];   sQ[wib][d0i+k]     = sq[k];
        sS[wib][128+d0i+k] = sm[4+k]; sQ[wib][128+d0i+k] = sq[4+k];
    }
    __syncthreads();
    float accS = 0.f, accQ = 0.f;
    #pragma unroll
    for (int w = 0; w < 8; w++) { accS += sS[w][threadIdx.x]; accQ += sQ[w][threadIdx.x]; }
    g_bpS[(size_t)blockIdx.x*DDIM + threadIdx.x] = accS;
    g_bpQ[(size_t)blockIdx.x*DDIM + threadIdx.x] = accQ;
}

// ---------------------------------------------------------------------------
// finB (float4): grid 64 blocks, 4 features per block. Thread t accumulates
// float4 rows b = t, t+256, ... (16B loads; line traffic amortized over 4
// features -> ~4x less L1<-L2 traffic than feature-per-block).
// ---------------------------------------------------------------------------
__global__ void __launch_bounds__(256) finB_kernel(const float* __restrict__ beta,
                                                   const float* __restrict__ gamma) {
    __shared__ float4 shS[8];
    __shared__ float4 shQ[8];
    const int fq   = blockIdx.x;          // feature quad: features 4fq..4fq+3
    const int tid  = threadIdx.x;
    const int lane = tid & 31;
    const int warp = tid >> 5;
    const float4* bpS4 = reinterpret_cast<const float4*>(g_bpS);
    const float4* bpQ4 = reinterpret_cast<const float4*>(g_bpQ);

    float4 s = make_float4(0.f, 0.f, 0.f, 0.f);
    float4 q = make_float4(0.f, 0.f, 0.f, 0.f);
    for (int b = tid; b < NBLK_B; b += 256) {
        float4 v = bpS4[(size_t)b*(DDIM/4) + fq];
        float4 w = bpQ4[(size_t)b*(DDIM/4) + fq];
        s.x += v.x; s.y += v.y; s.z += v.z; s.w += v.w;
        q.x += w.x; q.y += w.y; q.z += w.z; q.w += w.w;
    }
    warpsum4(s.x, s.y, s.z, s.w);
    warpsum4(q.x, q.y, q.z, q.w);
    if (lane == 0) { shS[warp] = s; shQ[warp] = q; }
    __syncthreads();
    if (tid == 0) {
        float4 S = shS[0], Q = shQ[0];
        #pragma unroll
        for (int i = 1; i < 8; i++) {
            S.x += shS[i].x; S.y += shS[i].y; S.z += shS[i].z; S.w += shS[i].w;
            Q.x += shQ[i].x; Q.y += shQ[i].y; Q.z += shQ[i].z; Q.w += shQ[i].w;
        }
        const float invN = 1.0f / (float)NROWS;
        const float gv = gamma[0];
        float muX = S.x*invN, muY = S.y*invN, muZ = S.z*invN, muW = S.w*invN;
        g_scale[4*fq+0] = gv * rsqrtf(Q.x*invN - muX*muX + 1e-5f);
        g_scale[4*fq+1] = gv * rsqrtf(Q.y*invN - muY*muY + 1e-5f);
        g_scale[4*fq+2] = gv * rsqrtf(Q.z*invN - muZ*muZ + 1e-5f);
        g_scale[4*fq+3] = gv * rsqrtf(Q.w*invN - muW*muW + 1e-5f);
        if (fq == 0) {
            float b0 = beta[0];
            g_ib  = 1.0f / (1.0f + b0);
            g_lab = -2.0f * (1.0f + b0);
        }
    }
}

// ---------------------------------------------------------------------------
// Pass C: reuses per-row (f, gc, c) from pass B — no dot/warpsum/acosh chain.
// ---------------------------------------------------------------------------
__global__ void __launch_bounds__(256) passC_kernel(const float* __restrict__ x,
                                                    const float* __restrict__ beta,
                                                    float* __restrict__ out) {
    const int lane = threadIdx.x & 31;
    const int gw   = (blockIdx.x * blockDim.x + threadIdx.x) >> 5;
    const int nw_  = (NBLK_C * 256) >> 5;   // 9472 warps

    float m[8], sc[8], bt[8];
    {
        float4 v;
        v = reinterpret_cast<const float4*>(g_mean)[lane];     m[0]=v.x; m[1]=v.y; m[2]=v.z; m[3]=v.w;
        v = reinterpret_cast<const float4*>(g_mean)[lane+32];  m[4]=v.x; m[5]=v.y; m[6]=v.z; m[7]=v.w;
        v = reinterpret_cast<const float4*>(g_scale)[lane];    sc[0]=v.x; sc[1]=v.y; sc[2]=v.z; sc[3]=v.w;
        v = reinterpret_cast<const float4*>(g_scale)[lane+32]; sc[4]=v.x; sc[5]=v.y; sc[6]=v.z; sc[7]=v.w;
        v = reinterpret_cast<const float4*>(beta)[lane];       bt[0]=v.x; bt[1]=v.y; bt[2]=v.z; bt[3]=v.w;
        v = reinterpret_cast<const float4*>(beta)[lane+32];    bt[4]=v.x; bt[5]=v.y; bt[6]=v.z; bt[7]=v.w;
    }
    const float ib  = g_ib;
    const float lab = g_lab;

    for (int row = gw; row < HALF; row += nw_) {
        const float4* rp1 = reinterpret_cast<const float4*>(x) + (size_t)row * (DDIM/4);
        const float4* rp2 = rp1 + (size_t)HALF * (DDIM/4);
        float a[8], b[8];
        {
            float4 v1 = __ldcs(rp1 + lane), v2 = __ldcs(rp1 + lane + 32);
            float4 u1 = __ldcs(rp2 + lane), u2 = __ldcs(rp2 + lane + 32);
            a[0]=v1.x; a[1]=v1.y; a[2]=v1.z; a[3]=v1.w;
            a[4]=v2.x; a[5]=v2.y; a[6]=v2.z; a[7]=v2.w;
            b[0]=u1.x; b[1]=u1.y; b[2]=u1.z; b[3]=u1.w;
            b[4]=u2.x; b[5]=u2.y; b[6]=u2.z; b[7]=u2.w;
        }
        const float4 s1 = __ldg(&g_rowsc[row]);
        const float4 s2 = __ldg(&g_rowsc[row + HALF]);
        const float f1 = s1.x, gc1 = s1.y, c1 = s1.z;
        const float f2 = s2.x, gc2 = s2.y, c2 = s2.z;

        // t scaled
        #pragma unroll
        for (int k = 0; k < 8; k++) {
            float t1 = fmaf(f1, a[k], -gc1*m[k]);
            float t2 = fmaf(f2, b[k], -gc2*m[k]);
            if (k == 0 && lane == 0) { t1 -= c1; t2 -= c2; }
            a[k] = t1 * sc[k];
            b[k] = t2 * sc[k];
        }
        float wt1 = __shfl_sync(0xffffffffu, a[0], 0);
        float wt2 = __shfl_sync(0xffffffffu, b[0], 0);

        // fused: q = linner(beta,w), n = linner(w,w)
        float q1 = bt[0]*a[0], q2 = bt[0]*b[0];
        float n1 = a[0]*a[0],  n2 = b[0]*b[0];
        if (lane == 0) { q1 = -q1; q2 = -q2; n1 = -n1; n2 = -n2; }
        #pragma unroll
        for (int k = 1; k < 8; k++) {
            q1 += bt[k]*a[k]; q2 += bt[k]*b[k];
            n1 += a[k]*a[k];  n2 += b[k]*b[k];
        }
        warpsum4(q1, n1, q2, n2);

        float cb1 = q1 * ib, cb2 = q2 * ib;
        float nn2_1 = n1 + 2.0f*cb1*(q1 - wt1) + cb1*cb1*lab;
        float nn2_2 = n2 + 2.0f*cb2*(q2 - wt2) + cb2*cb2*lab;
        float nn1 = sqrtf(fmaxf(nn2_1, 1e-7f));
        float nn2 = sqrtf(fmaxf(nn2_2, 1e-7f));
        float e1 = __expf(nn1), e2 = __expf(nn2);
        float ei1 = __frcp_rn(e1), ei2 = __frcp_rn(e2);
        float ch1 = 0.5f*(e1 + ei1), ch2 = 0.5f*(e2 + ei2);
        float sh1 = 0.5f*(e1 - ei1) * __frcp_rn(nn1);
        float sh2 = 0.5f*(e2 - ei2) * __frcp_rn(nn2);

        #pragma unroll
        for (int k = 0; k < 8; k++) {
            a[k] = fmaf(cb1, bt[k], a[k]);
            b[k] = fmaf(cb2, bt[k], b[k]);
            if (k == 0 && lane == 0) { a[0] += cb1; b[0] += cb2; }
        }

        float4* op1 = reinterpret_cast<float4*>(out) + (size_t)row * (DDIM/4);
        float4* op2 = op1 + (size_t)HALF * (DDIM/4);
        __stcs(op1 + lane,      make_float4(fmaf(ch1,bt[0],sh1*a[0]), fmaf(ch1,bt[1],sh1*a[1]),
                                            fmaf(ch1,bt[2],sh1*a[2]), fmaf(ch1,bt[3],sh1*a[3])));
        __stcs(op1 + lane + 32, make_float4(fmaf(ch1,bt[4],sh1*a[4]), fmaf(ch1,bt[5],sh1*a[5]),
                                            fmaf(ch1,bt[6],sh1*a[6]), fmaf(ch1,bt[7],sh1*a[7])));
        __stcs(op2 + lane,      make_float4(fmaf(ch2,bt[0],sh2*b[0]), fmaf(ch2,bt[1],sh2*b[1]),
                                            fmaf(ch2,bt[2],sh2*b[2]), fmaf(ch2,bt[3],sh2*b[3])));
        __stcs(op2 + lane + 32, make_float4(fmaf(ch2,bt[4],sh2*b[4]), fmaf(ch2,bt[5],sh2*b[5]),
                                            fmaf(ch2,bt[6],sh2*b[6]), fmaf(ch2,bt[7],sh2*b[7])));
    }
}

// ---------------------------------------------------------------------------
extern "C" void kernel_launch(void* const* d_in, const int* in_sizes, int n_in,
                              void* d_out, int out_size) {
    const float* x     = (const float*)d_in[0];
    const float* beta  = (const float*)d_in[1];
    const float* gamma = (const float*)d_in[2];
    float* out = (float*)d_out;

    dim3 gA(8, BATCH);
    passA_kernel<<<gA, 256>>>(x);
    a2_kernel<<<BATCH, 256>>>();
    passB_kernel<<<NBLK_B, 256>>>(x);
    finB_kernel<<<DDIM/4, 256>>>(beta, gamma);
    passC_kernel<<<NBLK_C, 256>>>(x, beta, out);
}